// round 4
// baseline (speedup 1.0000x reference)
#include <cuda_runtime.h>
#include <cuda_bf16.h>
#include <math.h>

// Problem constants
#define PB 8
#define PS 2048
#define PD 1024
#define PC 4096

// Tiling
#define BM 128
#define BN 128
#define BKT 16
#define NTHREADS 256

// ---------------------------------------------------------------------------
// GEMM1 (NT): S[m,n] = sum_k X[m,k] * L[n,k]
//   X: [M,K] row-major, L: [N,K] row-major, S: [M,N] row-major
//   M = B*S = 16384, N = C = 4096, K = D = 1024
// ---------------------------------------------------------------------------
__global__ __launch_bounds__(NTHREADS, 2)
void gemm1_nt(const float* __restrict__ X, const float* __restrict__ L,
              float* __restrict__ Sc, int M, int N, int K) {
    __shared__ float As[2][BKT][BM];
    __shared__ float Bs[2][BKT][BN];

    const int tid = threadIdx.x;
    const int bm = blockIdx.y * BM;
    const int bn = blockIdx.x * BN;

    // loader mapping: 128 rows x 16 k per tile; each thread: 2x float4 per matrix
    const int lr = tid >> 2;          // 0..63 (rows lr and lr+64)
    const int lk = (tid & 3) << 2;    // k offset 0,4,8,12

    const float* xg = X + (size_t)(bm + lr) * K + lk;
    const float* lg = L + (size_t)(bn + lr) * K + lk;
    const size_t rstep = (size_t)64 * K;

    float4 xa0 = *(const float4*)(xg);
    float4 xa1 = *(const float4*)(xg + rstep);
    float4 lb0 = *(const float4*)(lg);
    float4 lb1 = *(const float4*)(lg + rstep);

    // store transposed: As[k][m]
    As[0][lk + 0][lr] = xa0.x; As[0][lk + 1][lr] = xa0.y;
    As[0][lk + 2][lr] = xa0.z; As[0][lk + 3][lr] = xa0.w;
    As[0][lk + 0][lr + 64] = xa1.x; As[0][lk + 1][lr + 64] = xa1.y;
    As[0][lk + 2][lr + 64] = xa1.z; As[0][lk + 3][lr + 64] = xa1.w;
    Bs[0][lk + 0][lr] = lb0.x; Bs[0][lk + 1][lr] = lb0.y;
    Bs[0][lk + 2][lr] = lb0.z; Bs[0][lk + 3][lr] = lb0.w;
    Bs[0][lk + 0][lr + 64] = lb1.x; Bs[0][lk + 1][lr + 64] = lb1.y;
    Bs[0][lk + 2][lr + 64] = lb1.z; Bs[0][lk + 3][lr + 64] = lb1.w;
    __syncthreads();

    float acc[8][8];
    #pragma unroll
    for (int i = 0; i < 8; i++)
        #pragma unroll
        for (int j = 0; j < 8; j++) acc[i][j] = 0.0f;

    const int ty = tid >> 4;   // 0..15 (row group)
    const int tx = tid & 15;   // 0..15 (col group)
    const int nt = K / BKT;

    for (int t = 0; t < nt; ++t) {
        const int buf = t & 1;
        if (t + 1 < nt) {
            const float* xg2 = xg + (t + 1) * BKT;
            const float* lg2 = lg + (t + 1) * BKT;
            xa0 = *(const float4*)(xg2);
            xa1 = *(const float4*)(xg2 + rstep);
            lb0 = *(const float4*)(lg2);
            lb1 = *(const float4*)(lg2 + rstep);
        }
        #pragma unroll
        for (int kk = 0; kk < BKT; ++kk) {
            float4 a0 = *(const float4*)&As[buf][kk][ty * 8];
            float4 a1 = *(const float4*)&As[buf][kk][ty * 8 + 4];
            float4 b0 = *(const float4*)&Bs[buf][kk][tx * 8];
            float4 b1 = *(const float4*)&Bs[buf][kk][tx * 8 + 4];
            float av[8] = {a0.x, a0.y, a0.z, a0.w, a1.x, a1.y, a1.z, a1.w};
            float bv[8] = {b0.x, b0.y, b0.z, b0.w, b1.x, b1.y, b1.z, b1.w};
            #pragma unroll
            for (int i = 0; i < 8; i++)
                #pragma unroll
                for (int j = 0; j < 8; j++)
                    acc[i][j] = fmaf(av[i], bv[j], acc[i][j]);
        }
        if (t + 1 < nt) {
            const int nb = buf ^ 1;
            As[nb][lk + 0][lr] = xa0.x; As[nb][lk + 1][lr] = xa0.y;
            As[nb][lk + 2][lr] = xa0.z; As[nb][lk + 3][lr] = xa0.w;
            As[nb][lk + 0][lr + 64] = xa1.x; As[nb][lk + 1][lr + 64] = xa1.y;
            As[nb][lk + 2][lr + 64] = xa1.z; As[nb][lk + 3][lr + 64] = xa1.w;
            Bs[nb][lk + 0][lr] = lb0.x; Bs[nb][lk + 1][lr] = lb0.y;
            Bs[nb][lk + 2][lr] = lb0.z; Bs[nb][lk + 3][lr] = lb0.w;
            Bs[nb][lk + 0][lr + 64] = lb1.x; Bs[nb][lk + 1][lr + 64] = lb1.y;
            Bs[nb][lk + 2][lr + 64] = lb1.z; Bs[nb][lk + 3][lr + 64] = lb1.w;
        }
        __syncthreads();
    }

    #pragma unroll
    for (int i = 0; i < 8; i++) {
        size_t row = (size_t)(bm + ty * 8 + i);
        float4 c0 = make_float4(acc[i][0], acc[i][1], acc[i][2], acc[i][3]);
        float4 c1 = make_float4(acc[i][4], acc[i][5], acc[i][6], acc[i][7]);
        *(float4*)&Sc[row * N + bn + tx * 8] = c0;
        *(float4*)&Sc[row * N + bn + tx * 8 + 4] = c1;
    }
}

// ---------------------------------------------------------------------------
// Row softmax over C=4096, in place. One block (256 threads) per row.
// ---------------------------------------------------------------------------
__global__ __launch_bounds__(256)
void softmax4096(float* __restrict__ A) {
    const int C = PC;
    float* row = A + (size_t)blockIdx.x * C;
    const int tid = threadIdx.x;
    const int lane = tid & 31;
    const int warp = tid >> 5;

    __shared__ float redmax[8];
    __shared__ float redsum[8];

    float4 v[4];
    float mx = -1e30f;
    #pragma unroll
    for (int j = 0; j < 4; j++) {
        v[j] = ((const float4*)row)[tid + j * 256];
        mx = fmaxf(mx, fmaxf(fmaxf(v[j].x, v[j].y), fmaxf(v[j].z, v[j].w)));
    }
    #pragma unroll
    for (int o = 16; o > 0; o >>= 1)
        mx = fmaxf(mx, __shfl_xor_sync(0xFFFFFFFFu, mx, o));
    if (lane == 0) redmax[warp] = mx;
    __syncthreads();
    mx = redmax[0];
    #pragma unroll
    for (int w = 1; w < 8; w++) mx = fmaxf(mx, redmax[w]);

    float s = 0.0f;
    #pragma unroll
    for (int j = 0; j < 4; j++) {
        v[j].x = __expf(v[j].x - mx);
        v[j].y = __expf(v[j].y - mx);
        v[j].z = __expf(v[j].z - mx);
        v[j].w = __expf(v[j].w - mx);
        s += (v[j].x + v[j].y) + (v[j].z + v[j].w);
    }
    #pragma unroll
    for (int o = 16; o > 0; o >>= 1)
        s += __shfl_xor_sync(0xFFFFFFFFu, s, o);
    if (lane == 0) redsum[warp] = s;
    __syncthreads();
    s = redsum[0];
    #pragma unroll
    for (int w = 1; w < 8; w++) s += redsum[w];

    const float rinv = 1.0f / s;
    #pragma unroll
    for (int j = 0; j < 4; j++) {
        v[j].x *= rinv; v[j].y *= rinv; v[j].z *= rinv; v[j].w *= rinv;
        ((float4*)row)[tid + j * 256] = v[j];
    }
}

// ---------------------------------------------------------------------------
// GEMM2 (TN), batched over z: Out[m,n] = sum_k A[k,m] * Xb[k,n]
//   A: [K,M] row-major (scores/softmax, K=S, M=C), Xb: [K,N] row-major (N=D)
// ---------------------------------------------------------------------------
__global__ __launch_bounds__(NTHREADS, 2)
void gemm2_tn(const float* __restrict__ Afull, const float* __restrict__ Xfull,
              float* __restrict__ Ofull, int M, int N, int K) {
    const int b = blockIdx.z;
    const float* A = Afull + (size_t)b * K * M;   // [S, C]
    const float* Xb = Xfull + (size_t)b * K * N;  // [S, D]
    float* O = Ofull + (size_t)b * M * N;         // [C, D]

    __shared__ float As[2][BKT][BM];
    __shared__ float Bs[2][BKT][BN];

    const int tid = threadIdx.x;
    const int bm = blockIdx.y * BM;
    const int bn = blockIdx.x * BN;

    // loader: rows r and r+8 (k dim), 32 float4 across 128 cols
    const int r = tid >> 5;           // 0..7
    const int c = (tid & 31) << 2;    // 0..124

    const float* ag = A + (size_t)r * M + bm + c;
    const float* bg = Xb + (size_t)r * N + bn + c;
    const size_t astep = (size_t)8 * M;
    const size_t bstep = (size_t)8 * N;

    float4 a0 = *(const float4*)(ag);
    float4 a1 = *(const float4*)(ag + astep);
    float4 b0 = *(const float4*)(bg);
    float4 b1 = *(const float4*)(bg + bstep);
    *(float4*)&As[0][r][c] = a0;
    *(float4*)&As[0][r + 8][c] = a1;
    *(float4*)&Bs[0][r][c] = b0;
    *(float4*)&Bs[0][r + 8][c] = b1;
    __syncthreads();

    float acc[8][8];
    #pragma unroll
    for (int i = 0; i < 8; i++)
        #pragma unroll
        for (int j = 0; j < 8; j++) acc[i][j] = 0.0f;

    const int ty = tid >> 4;
    const int tx = tid & 15;
    const int nt = K / BKT;

    for (int t = 0; t < nt; ++t) {
        const int buf = t & 1;
        if (t + 1 < nt) {
            const float* ag2 = ag + (size_t)(t + 1) * BKT * M;
            const float* bg2 = bg + (size_t)(t + 1) * BKT * N;
            a0 = *(const float4*)(ag2);
            a1 = *(const float4*)(ag2 + astep);
            b0 = *(const float4*)(bg2);
            b1 = *(const float4*)(bg2 + bstep);
        }
        #pragma unroll
        for (int kk = 0; kk < BKT; ++kk) {
            float4 av0 = *(const float4*)&As[buf][kk][ty * 8];
            float4 av1 = *(const float4*)&As[buf][kk][ty * 8 + 4];
            float4 bv0 = *(const float4*)&Bs[buf][kk][tx * 8];
            float4 bv1 = *(const float4*)&Bs[buf][kk][tx * 8 + 4];
            float av[8] = {av0.x, av0.y, av0.z, av0.w, av1.x, av1.y, av1.z, av1.w};
            float bv[8] = {bv0.x, bv0.y, bv0.z, bv0.w, bv1.x, bv1.y, bv1.z, bv1.w};
            #pragma unroll
            for (int i = 0; i < 8; i++)
                #pragma unroll
                for (int j = 0; j < 8; j++)
                    acc[i][j] = fmaf(av[i], bv[j], acc[i][j]);
        }
        if (t + 1 < nt) {
            const int nb = buf ^ 1;
            *(float4*)&As[nb][r][c] = a0;
            *(float4*)&As[nb][r + 8][c] = a1;
            *(float4*)&Bs[nb][r][c] = b0;
            *(float4*)&Bs[nb][r + 8][c] = b1;
        }
        __syncthreads();
    }

    #pragma unroll
    for (int i = 0; i < 8; i++) {
        size_t row = (size_t)(bm + ty * 8 + i);
        float4 c0 = make_float4(acc[i][0], acc[i][1], acc[i][2], acc[i][3]);
        float4 c1 = make_float4(acc[i][4], acc[i][5], acc[i][6], acc[i][7]);
        *(float4*)&O[row * N + bn + tx * 8] = c0;
        *(float4*)&O[row * N + bn + tx * 8 + 4] = c1;
    }
}

// ---------------------------------------------------------------------------
// Launch: scores -> A region of d_out (scratch), softmax in place, then GEMM2.
// d_out layout: [output (B*C*D floats) | A (B*S*C floats)]
// ---------------------------------------------------------------------------
extern "C" void kernel_launch(void* const* d_in, const int* in_sizes, int n_in,
                              void* d_out, int out_size) {
    const float* x = (const float*)d_in[0];        // [B,S,D]
    const float* lab = (const float*)d_in[1];      // [C,D]
    float* out = (float*)d_out;

    float* Aout = out + (size_t)PB * PC * PD;      // [B,S,C]

    // GEMM1: scores into A region
    dim3 g1(PC / BN, (PB * PS) / BM);
    gemm1_nt<<<g1, NTHREADS>>>(x, lab, Aout, PB * PS, PC, PD);

    // softmax over C, in place
    softmax4096<<<PB * PS, 256>>>(Aout);

    // GEMM2: output = A^T @ x per batch
    dim3 g2(PD / BN, PC / BM, PB);
    gemm2_tn<<<g2, NTHREADS>>>(Aout, x, out, PC, PD, PS);
}

// round 6
// speedup vs baseline: 2.2244x; 2.2244x over previous
#include <cuda_runtime.h>
#include <cuda_fp16.h>
#include <cstdint>
#include <math.h>

// Problem constants
#define PB 8
#define PS 2048
#define PD 1024
#define PC 4096

// GEMM tiling
#define BM 128
#define BN 128
#define BK 32                     // k-halves per stage
#define PITCH 40                  // halves per smem row (80 bytes, conflict-free)
#define OPB (128 * PITCH * 2)     // bytes per operand tile   = 10240
#define STAGE_BYTES (4 * OPB)     // Ah|Al|Bh|Bl              = 40960
#define GSMEM (2 * STAGE_BYTES)   // two stages               = 81920

// ===========================================================================
// helpers
// ===========================================================================
__device__ __forceinline__ uint32_t smem_u32(const void* p) {
    uint32_t a;
    asm("{ .reg .u64 t; cvta.to.shared.u64 t, %1; cvt.u32.u64 %0, t; }"
        : "=r"(a) : "l"(p));
    return a;
}

__device__ __forceinline__ void cp16(uint32_t dst, const void* src) {
    asm volatile("cp.async.cg.shared.global [%0], [%1], 16;\n" :: "r"(dst), "l"(src));
}

#define CP_COMMIT() asm volatile("cp.async.commit_group;\n" ::: "memory")
#define CP_WAIT(n)  asm volatile("cp.async.wait_group %0;\n" :: "n"(n) : "memory")

#define LDMX4(r0, r1, r2, r3, addr) \
    asm volatile("ldmatrix.sync.aligned.m8n8.x4.shared.b16 {%0,%1,%2,%3}, [%4];" \
        : "=r"(r0), "=r"(r1), "=r"(r2), "=r"(r3) : "r"(addr))

#define MMA16816(d, a, b0, b1) \
    asm volatile("mma.sync.aligned.m16n8k16.row.col.f32.f16.f16.f32 " \
        "{%0,%1,%2,%3}, {%4,%5,%6,%7}, {%8,%9}, {%0,%1,%2,%3};" \
        : "+f"((d)[0]), "+f"((d)[1]), "+f"((d)[2]), "+f"((d)[3]) \
        : "r"((a)[0]), "r"((a)[1]), "r"((a)[2]), "r"((a)[3]), "r"(b0), "r"(b1))

// ===========================================================================
// Scratch (__device__ globals — no runtime allocation)
// ===========================================================================
__device__ __half g_Xh [(size_t)PB * PS * PD];   // X split hi      [B*S, D]
__device__ __half g_Xl [(size_t)PB * PS * PD];   // X split lo
__device__ __half g_Lh [(size_t)PC * PD];        // label split hi  [C, D]
__device__ __half g_Ll [(size_t)PC * PD];
__device__ __half g_XhT[(size_t)PB * PD * PS];   // X^T split       [B][D, S]
__device__ __half g_XlT[(size_t)PB * PD * PS];
__device__ __half g_AhT[(size_t)PB * PC * PS];   // A^T split       [B][C, S]
__device__ __half g_AlT[(size_t)PB * PC * PS];

// ===========================================================================
// fp32 -> fp16 hi/lo split (lo unscaled; |lo| <= 2^-12|x|, fp16-representable)
// ===========================================================================
__global__ void split_kernel(const float* __restrict__ in, __half* __restrict__ ho,
                             __half* __restrict__ lo, int n4) {
    int i = blockIdx.x * blockDim.x + threadIdx.x;
    if (i >= n4) return;
    float4 v = ((const float4*)in)[i];
    __half h0 = __float2half_rn(v.x), h1 = __float2half_rn(v.y);
    __half h2 = __float2half_rn(v.z), h3 = __float2half_rn(v.w);
    __half l0 = __float2half_rn(v.x - __half2float(h0));
    __half l1 = __float2half_rn(v.y - __half2float(h1));
    __half l2 = __float2half_rn(v.z - __half2float(h2));
    __half l3 = __float2half_rn(v.w - __half2float(h3));
    ((__half2*)ho)[2 * i]     = __halves2half2(h0, h1);
    ((__half2*)ho)[2 * i + 1] = __halves2half2(h2, h3);
    ((__half2*)lo)[2 * i]     = __halves2half2(l0, l1);
    ((__half2*)lo)[2 * i + 1] = __halves2half2(l2, l3);
}

// ===========================================================================
// Transposing fp32 -> fp16 hi/lo split: src [srcRows, srcCols] -> dst [srcCols, srcRows]
// ===========================================================================
__global__ __launch_bounds__(256)
void transpose_split(const float* __restrict__ src, __half* __restrict__ hT,
                     __half* __restrict__ lT, int srcRows, int srcCols,
                     size_t srcBatch, size_t dstBatch) {
    __shared__ float tile[32][65];
    int b = blockIdx.z;
    src += (size_t)b * srcBatch;
    hT  += (size_t)b * dstBatch;
    lT  += (size_t)b * dstBatch;
    int c0 = blockIdx.x * 32;
    int r0 = blockIdx.y * 64;
    int t = threadIdx.x;
    int lc = t & 31, lr = t >> 5;
    #pragma unroll
    for (int j = 0; j < 8; ++j)
        tile[lc][lr + 8 * j] = src[(size_t)(r0 + lr + 8 * j) * srcCols + c0 + lc];
    __syncthreads();
    int oc = t >> 3, rp = t & 7;
    #pragma unroll
    for (int j = 0; j < 4; ++j) {
        int rr = (rp + 8 * j) * 2;
        float f0 = tile[oc][rr], f1 = tile[oc][rr + 1];
        __half h0 = __float2half_rn(f0), h1 = __float2half_rn(f1);
        __half l0 = __float2half_rn(f0 - __half2float(h0));
        __half l1 = __float2half_rn(f1 - __half2float(h1));
        size_t o = (size_t)(c0 + oc) * srcRows + r0 + rr;
        *(__half2*)(hT + o) = __halves2half2(h0, h1);
        *(__half2*)(lT + o) = __halves2half2(l0, l1);
    }
}

// ===========================================================================
// HMMA split-fp16 GEMM:  Out[m,n] = sum_k (Ah+Al)[m,k] * (Bh+Bl)[n,k]
//   (single fp32 accumulator: hi*hi + hi*lo + lo*hi)
// A: [M,K] K-major halves, B: [N,K] K-major halves, Out fp32 [M,N].
// CTA 128x128, 8 warps of 32x64, BK=32, 2-stage cp.async pipeline.
// ===========================================================================
__global__ __launch_bounds__(256, 2)
void gemm_hmma_split(const __half* __restrict__ Ah, const __half* __restrict__ Al,
                     const __half* __restrict__ Bh, const __half* __restrict__ Bl,
                     float* __restrict__ Out,
                     int lda, int ldb, int ldc, int K,
                     size_t aBatch, size_t bBatch, size_t cBatch) {
    extern __shared__ char smem[];
    const uint32_t sb = smem_u32(smem);
    const int tid = threadIdx.x;
    const int lane = tid & 31;
    const int wid = tid >> 5;

    const int b = blockIdx.z;
    Ah += (size_t)b * aBatch;  Al += (size_t)b * aBatch;
    Bh += (size_t)b * bBatch;  Bl += (size_t)b * bBatch;
    Out += (size_t)b * cBatch;

    const int bm = blockIdx.y * BM;
    const int bn = blockIdx.x * BN;

    // ---- loader mapping: each thread: 2 rows x 1 16B-chunk per operand ----
    const int rA = tid >> 2;               // 0..63 (rows rA, rA+64)
    const int ch = (tid & 3) * 8;          // k-offset in halves
    const uint32_t sOff = (uint32_t)rA * (PITCH * 2) + (tid & 3) * 16;

    const __half* pAh = Ah + (size_t)(bm + rA) * lda + ch;
    const __half* pAl = Al + (size_t)(bm + rA) * lda + ch;
    const __half* pBh = Bh + (size_t)(bn + rA) * ldb + ch;
    const __half* pBl = Bl + (size_t)(bn + rA) * ldb + ch;
    const size_t aStep = (size_t)64 * lda;
    const size_t bStep = (size_t)64 * ldb;

    const int warpM = (wid & 3) * 32;
    const int warpN = (wid >> 2) * 64;

    float acc[2][8][4];
    #pragma unroll
    for (int i = 0; i < 2; i++)
        #pragma unroll
        for (int j = 0; j < 8; j++)
            #pragma unroll
            for (int k = 0; k < 4; k++) acc[i][j][k] = 0.0f;

    const int nIter = K / BK;

    // prologue: stage 0
    {
        const uint32_t st = sb;
        cp16(st + 0 * OPB + sOff, pAh);
        cp16(st + 0 * OPB + sOff + 64 * PITCH * 2, pAh + aStep);
        cp16(st + 1 * OPB + sOff, pAl);
        cp16(st + 1 * OPB + sOff + 64 * PITCH * 2, pAl + aStep);
        cp16(st + 2 * OPB + sOff, pBh);
        cp16(st + 2 * OPB + sOff + 64 * PITCH * 2, pBh + bStep);
        cp16(st + 3 * OPB + sOff, pBl);
        cp16(st + 3 * OPB + sOff + 64 * PITCH * 2, pBl + bStep);
        CP_COMMIT();
    }

    // ldmatrix lane address pieces:  row += lane&15, byte-col += lane&16
    const uint32_t lrow = (uint32_t)(lane & 15) * (PITCH * 2) + (lane & 16);

    for (int t = 0; t < nIter; ++t) {
        if (t + 1 < nIter) {
            const uint32_t st = sb + ((t + 1) & 1) * STAGE_BYTES;
            const size_t ko = (size_t)(t + 1) * BK;
            cp16(st + 0 * OPB + sOff, pAh + ko);
            cp16(st + 0 * OPB + sOff + 64 * PITCH * 2, pAh + ko + aStep);
            cp16(st + 1 * OPB + sOff, pAl + ko);
            cp16(st + 1 * OPB + sOff + 64 * PITCH * 2, pAl + ko + aStep);
            cp16(st + 2 * OPB + sOff, pBh + ko);
            cp16(st + 2 * OPB + sOff + 64 * PITCH * 2, pBh + ko + bStep);
            cp16(st + 3 * OPB + sOff, pBl + ko);
            cp16(st + 3 * OPB + sOff + 64 * PITCH * 2, pBl + ko + bStep);
            CP_COMMIT();
            CP_WAIT(1);
        } else {
            CP_WAIT(0);
        }
        __syncthreads();

        const uint32_t s0 = sb + (t & 1) * STAGE_BYTES;
        #pragma unroll
        for (int kk = 0; kk < 2; ++kk) {           // two k16 steps per BK=32
            uint32_t ah[2][4], al[2][4];
            #pragma unroll
            for (int mt = 0; mt < 2; ++mt) {
                const uint32_t aaddr = s0 + (uint32_t)(warpM + mt * 16) * (PITCH * 2)
                                       + lrow + kk * 32;
                LDMX4(ah[mt][0], ah[mt][1], ah[mt][2], ah[mt][3], aaddr + 0 * OPB);
                LDMX4(al[mt][0], al[mt][1], al[mt][2], al[mt][3], aaddr + 1 * OPB);
            }
            #pragma unroll
            for (int g = 0; g < 4; ++g) {
                uint32_t bh0, bh1, bh2, bh3, bl0, bl1, bl2, bl3;
                const uint32_t baddr = s0 + (uint32_t)(warpN + g * 16) * (PITCH * 2)
                                       + lrow + kk * 32;
                LDMX4(bh0, bh1, bh2, bh3, baddr + 2 * OPB);
                LDMX4(bl0, bl1, bl2, bl3, baddr + 3 * OPB);
                #pragma unroll
                for (int mt = 0; mt < 2; ++mt) {
                    MMA16816(acc[mt][2 * g],     ah[mt], bh0, bh2);
                    MMA16816(acc[mt][2 * g],     ah[mt], bl0, bl2);
                    MMA16816(acc[mt][2 * g],     al[mt], bh0, bh2);
                    MMA16816(acc[mt][2 * g + 1], ah[mt], bh1, bh3);
                    MMA16816(acc[mt][2 * g + 1], ah[mt], bl1, bl3);
                    MMA16816(acc[mt][2 * g + 1], al[mt], bh1, bh3);
                }
            }
        }
        __syncthreads();
    }

    // ---- epilogue: direct fp32 stores (quad-contiguous 32B segments) ----
    #pragma unroll
    for (int mt = 0; mt < 2; ++mt) {
        #pragma unroll
        for (int nf = 0; nf < 8; ++nf) {
            const int row = bm + warpM + mt * 16 + (lane >> 2);
            const int col = bn + warpN + nf * 8 + (lane & 3) * 2;
            *(float2*)&Out[(size_t)row * ldc + col] =
                make_float2(acc[mt][nf][0], acc[mt][nf][1]);
            *(float2*)&Out[(size_t)(row + 8) * ldc + col] =
                make_float2(acc[mt][nf][2], acc[mt][nf][3]);
        }
    }
}

// ---------------------------------------------------------------------------
// Row softmax over C=4096, in place. One block (256 threads) per row.
// ---------------------------------------------------------------------------
__global__ __launch_bounds__(256)
void softmax4096(float* __restrict__ A) {
    const int C = PC;
    float* row = A + (size_t)blockIdx.x * C;
    const int tid = threadIdx.x;
    const int lane = tid & 31;
    const int warp = tid >> 5;

    __shared__ float redmax[8];
    __shared__ float redsum[8];

    float4 v[4];
    float mx = -1e30f;
    #pragma unroll
    for (int j = 0; j < 4; j++) {
        v[j] = ((const float4*)row)[tid + j * 256];
        mx = fmaxf(mx, fmaxf(fmaxf(v[j].x, v[j].y), fmaxf(v[j].z, v[j].w)));
    }
    #pragma unroll
    for (int o = 16; o > 0; o >>= 1)
        mx = fmaxf(mx, __shfl_xor_sync(0xFFFFFFFFu, mx, o));
    if (lane == 0) redmax[warp] = mx;
    __syncthreads();
    mx = redmax[0];
    #pragma unroll
    for (int w = 1; w < 8; w++) mx = fmaxf(mx, redmax[w]);

    float s = 0.0f;
    #pragma unroll
    for (int j = 0; j < 4; j++) {
        v[j].x = __expf(v[j].x - mx);
        v[j].y = __expf(v[j].y - mx);
        v[j].z = __expf(v[j].z - mx);
        v[j].w = __expf(v[j].w - mx);
        s += (v[j].x + v[j].y) + (v[j].z + v[j].w);
    }
    #pragma unroll
    for (int o = 16; o > 0; o >>= 1)
        s += __shfl_xor_sync(0xFFFFFFFFu, s, o);
    if (lane == 0) redsum[warp] = s;
    __syncthreads();
    s = redsum[0];
    #pragma unroll
    for (int w = 1; w < 8; w++) s += redsum[w];

    const float rinv = 1.0f / s;
    #pragma unroll
    for (int j = 0; j < 4; j++) {
        v[j].x *= rinv; v[j].y *= rinv; v[j].z *= rinv; v[j].w *= rinv;
        ((float4*)row)[tid + j * 256] = v[j];
    }
}

// ===========================================================================
// Launch.  d_out layout: [output (B*C*D floats) | A (B*S*C floats)]
// ===========================================================================
extern "C" void kernel_launch(void* const* d_in, const int* in_sizes, int n_in,
                              void* d_out, int out_size) {
    const float* x = (const float*)d_in[0];    // [B,S,D]
    const float* lab = (const float*)d_in[1];  // [C,D]
    float* out = (float*)d_out;
    float* Aout = out + (size_t)PB * PC * PD;  // [B*S, C]

    void *pXh, *pXl, *pLh, *pLl, *pXhT, *pXlT, *pAhT, *pAlT;
    cudaGetSymbolAddress(&pXh, g_Xh);   cudaGetSymbolAddress(&pXl, g_Xl);
    cudaGetSymbolAddress(&pLh, g_Lh);   cudaGetSymbolAddress(&pLl, g_Ll);
    cudaGetSymbolAddress(&pXhT, g_XhT); cudaGetSymbolAddress(&pXlT, g_XlT);
    cudaGetSymbolAddress(&pAhT, g_AhT); cudaGetSymbolAddress(&pAlT, g_AlT);

    cudaFuncSetAttribute(gemm_hmma_split,
                         cudaFuncAttributeMaxDynamicSharedMemorySize, GSMEM);

    // 1. fp16 splits of X and L
    split_kernel<<<(PB * PS * PD / 4 + 255) / 256, 256>>>(
        x, (__half*)pXh, (__half*)pXl, PB * PS * PD / 4);
    split_kernel<<<(PC * PD / 4 + 255) / 256, 256>>>(
        lab, (__half*)pLh, (__half*)pLl, PC * PD / 4);

    // 2. X^T split per batch: [S,D] -> [D,S]
    {
        dim3 g(PD / 32, PS / 64, PB);
        transpose_split<<<g, 256>>>(x, (__half*)pXhT, (__half*)pXlT,
                                    PS, PD, (size_t)PS * PD, (size_t)PD * PS);
    }

    // 3. GEMM1: scores[B*S, C] = X @ L^T
    {
        dim3 g(PC / BN, (PB * PS) / BM, 1);
        gemm_hmma_split<<<g, 256, GSMEM>>>(
            (const __half*)pXh, (const __half*)pXl,
            (const __half*)pLh, (const __half*)pLl,
            Aout, PD, PD, PC, PD, 0, 0, 0);
    }

    // 4. softmax over C, in place
    softmax4096<<<PB * PS, 256>>>(Aout);

    // 5. A^T split per batch: [S,C] -> [C,S]
    {
        dim3 g(PC / 32, PS / 64, PB);
        transpose_split<<<g, 256>>>(Aout, (__half*)pAhT, (__half*)pAlT,
                                    PS, PC, (size_t)PS * PC, (size_t)PC * PS);
    }

    // 6. GEMM2 per batch: out[C, D] = A^T @ X
    {
        dim3 g(PD / BN, PC / BM, PB);
        gemm_hmma_split<<<g, 256, GSMEM>>>(
            (const __half*)pAhT, (const __half*)pAlT,
            (const __half*)pXhT, (const __half*)pXlT,
            out, PS, PS, PD, PS,
            (size_t)PC * PS, (size_t)PD * PS, (size_t)PC * PD);
    }
}

// round 10
// speedup vs baseline: 3.2407x; 1.4569x over previous
#include <cuda_runtime.h>
#include <cuda_fp16.h>
#include <cstdint>
#include <math.h>

// Problem constants
#define PB 8
#define PS 2048
#define PD 1024
#define PC 4096

#define BM 128
#define BN 128

// ===========================================================================
// helpers
// ===========================================================================
__device__ __forceinline__ uint32_t smem_u32(const void* p) {
    uint32_t a;
    asm("{ .reg .u64 t; cvta.to.shared.u64 t, %1; cvt.u32.u64 %0, t; }"
        : "=r"(a) : "l"(p));
    return a;
}

__device__ __forceinline__ void cp16(uint32_t dst, const void* src) {
    asm volatile("cp.async.cg.shared.global [%0], [%1], 16;\n" :: "r"(dst), "l"(src));
}

#define CP_COMMIT() asm volatile("cp.async.commit_group;\n" ::: "memory")
#define CP_WAIT_ALL() asm volatile("cp.async.wait_group 0;\n" ::: "memory")

#define LDMX4(r0, r1, r2, r3, addr) \
    asm volatile("ldmatrix.sync.aligned.m8n8.x4.shared.b16 {%0,%1,%2,%3}, [%4];" \
        : "=r"(r0), "=r"(r1), "=r"(r2), "=r"(r3) : "r"(addr))

#define MMA16816(d, a, b0, b1) \
    asm volatile("mma.sync.aligned.m16n8k16.row.col.f32.f16.f16.f32 " \
        "{%0,%1,%2,%3}, {%4,%5,%6,%7}, {%8,%9}, {%0,%1,%2,%3};" \
        : "+f"((d)[0]), "+f"((d)[1]), "+f"((d)[2]), "+f"((d)[3]) \
        : "r"((a)[0]), "r"((a)[1]), "r"((a)[2]), "r"((a)[3]), "r"(b0), "r"(b1))

// ===========================================================================
// Scratch (__device__ globals — no runtime allocation)
// ===========================================================================
__device__ __half g_Xh [(size_t)PB * PS * PD];   // X split hi      [B*S, D]
__device__ __half g_Xl [(size_t)PB * PS * PD];   // X split lo
__device__ __half g_Lh [(size_t)PC * PD];        // label split hi  [C, D]
__device__ __half g_Ll [(size_t)PC * PD];
__device__ __half g_XhT[(size_t)PB * PD * PS];   // X^T hi          [B][D, S]
__device__ __half g_AhT[(size_t)PB * PC * PS];   // A^T hi          [B][C, S]

// ===========================================================================
// fp32 -> fp16 hi/lo split (lo unscaled; |lo| <= 2^-12|x|)
// ===========================================================================
__global__ void split_kernel(const float* __restrict__ in, __half* __restrict__ ho,
                             __half* __restrict__ lo, int n4) {
    int i = blockIdx.x * blockDim.x + threadIdx.x;
    if (i >= n4) return;
    float4 v = ((const float4*)in)[i];
    __half h0 = __float2half_rn(v.x), h1 = __float2half_rn(v.y);
    __half h2 = __float2half_rn(v.z), h3 = __float2half_rn(v.w);
    __half l0 = __float2half_rn(v.x - __half2float(h0));
    __half l1 = __float2half_rn(v.y - __half2float(h1));
    __half l2 = __float2half_rn(v.z - __half2float(h2));
    __half l3 = __float2half_rn(v.w - __half2float(h3));
    ((__half2*)ho)[2 * i]     = __halves2half2(h0, h1);
    ((__half2*)ho)[2 * i + 1] = __halves2half2(h2, h3);
    ((__half2*)lo)[2 * i]     = __halves2half2(l0, l1);
    ((__half2*)lo)[2 * i + 1] = __halves2half2(l2, l3);
}

// ===========================================================================
// Transposing fp32 -> fp16 (hi only): src [srcRows, srcCols] -> dst [srcCols, srcRows]
// ===========================================================================
__global__ __launch_bounds__(256)
void transpose_h(const float* __restrict__ src, __half* __restrict__ hT,
                 int srcRows, int srcCols, size_t srcBatch, size_t dstBatch) {
    __shared__ float tile[32][65];
    int b = blockIdx.z;
    src += (size_t)b * srcBatch;
    hT  += (size_t)b * dstBatch;
    int c0 = blockIdx.x * 32;
    int r0 = blockIdx.y * 64;
    int t = threadIdx.x;
    int lc = t & 31, lr = t >> 5;
    #pragma unroll
    for (int j = 0; j < 8; ++j)
        tile[lc][lr + 8 * j] = src[(size_t)(r0 + lr + 8 * j) * srcCols + c0 + lc];
    __syncthreads();
    int oc = t >> 3, rp = t & 7;
    #pragma unroll
    for (int j = 0; j < 4; ++j) {
        int rr = (rp + 8 * j) * 2;
        float f0 = tile[oc][rr], f1 = tile[oc][rr + 1];
        __half h0 = __float2half_rn(f0), h1 = __float2half_rn(f1);
        size_t o = (size_t)(c0 + oc) * srcRows + r0 + rr;
        *(__half2*)(hT + o) = __halves2half2(h0, h1);
    }
}

// ===========================================================================
// HMMA GEMM, templated:
//   NT=3: Out = (Ah+Al)*(Bh+Bl)^T  via  ah*bh + ah*bl + al*bh  (split-fp16)
//   NT=1: Out = Ah*Bh^T                                         (pure fp16)
// A: [M,K] K-major halves, B: [N,K] K-major halves, Out fp32 [M,N].
// CTA 128x128, 8 warps (32x64), BKH k-halves/stage, 2 stages,
// ONE __syncthreads per iter; loads issued post-sync overlap full compute.
// ===========================================================================
template<int NT, int BKH>
__global__ __launch_bounds__(256, 2)
void gemm_hmma(const __half* __restrict__ Ah, const __half* __restrict__ Al,
               const __half* __restrict__ Bh, const __half* __restrict__ Bl,
               float* __restrict__ Out,
               int lda, int ldb, int ldc, int K,
               size_t aBatch, size_t bBatch, size_t cBatch) {
    constexpr int PIT   = BKH + 8;            // halves per smem row (conflict-free)
    constexpr int TILEB = 128 * PIT * 2;      // bytes per operand tile
    constexpr int NOP   = (NT == 3) ? 4 : 2;  // tiles per stage
    constexpr int STB   = NOP * TILEB;        // stage bytes
    constexpr int CPR   = BKH / 8;            // 16B chunks per row
    constexpr int RST   = 256 / CPR;          // rows per loader pass

    extern __shared__ char smem[];
    const uint32_t sb = smem_u32(smem);
    const int tid = threadIdx.x;
    const int lane = tid & 31;
    const int wid = tid >> 5;

    const int b = blockIdx.z;
    Ah += (size_t)b * aBatch;
    Bh += (size_t)b * bBatch;
    Out += (size_t)b * cBatch;
    if (NT == 3) { Al += (size_t)b * aBatch; Bl += (size_t)b * bBatch; }

    const int bm = blockIdx.y * BM;
    const int bn = blockIdx.x * BN;

    // loader mapping
    const int r0 = tid / CPR;
    const int cb = (tid % CPR) * 16;               // byte col in smem row
    const int chalves = (tid % CPR) * 8;           // k-offset (halves)
    const uint32_t sOffBase = (uint32_t)r0 * (PIT * 2) + cb;

    const __half* pAh = Ah + (size_t)(bm + r0) * lda + chalves;
    const __half* pBh = Bh + (size_t)(bn + r0) * ldb + chalves;
    const __half* pAl = (NT == 3) ? Al + (size_t)(bm + r0) * lda + chalves : pAh;
    const __half* pBl = (NT == 3) ? Bl + (size_t)(bn + r0) * ldb + chalves : pBh;

    const int warpM = (wid & 3) * 32;
    const int warpN = (wid >> 2) * 64;

    float acc[2][8][4];
    #pragma unroll
    for (int i = 0; i < 2; i++)
        #pragma unroll
        for (int j = 0; j < 8; j++)
            #pragma unroll
            for (int k = 0; k < 4; k++) acc[i][j][k] = 0.0f;

    const int nIter = K / BKH;

    // ---- loader macro: issue all cp.asyncs for stage buffer `st`, k-off ko ----
    #define ISSUE_STAGE(st, ko) do {                                             \
        _Pragma("unroll")                                                        \
        for (int rr = 0; rr < 128; rr += RST) {                                  \
            const uint32_t so = sOffBase + (uint32_t)rr * (PIT * 2);             \
            cp16((st) + 0 * TILEB + so, pAh + (size_t)rr * lda + (ko));          \
            if (NT == 3) cp16((st) + 2 * TILEB + so, pAl + (size_t)rr * lda + (ko)); \
            cp16((st) + 1 * TILEB + so, pBh + (size_t)rr * ldb + (ko));          \
            if (NT == 3) cp16((st) + 3 * TILEB + so, pBl + (size_t)rr * ldb + (ko)); \
        }                                                                        \
        CP_COMMIT();                                                             \
    } while (0)

    // prologue: stage 0
    ISSUE_STAGE(sb, 0);

    const uint32_t lrow = (uint32_t)(lane & 15) * (PIT * 2) + (lane & 16);

    for (int t = 0; t < nIter; ++t) {
        CP_WAIT_ALL();          // stage t data resident
        __syncthreads();        // all warps done with compute(t-1); safe to refill

        if (t + 1 < nIter) {
            const uint32_t st = sb + ((t + 1) & 1) * STB;
            ISSUE_STAGE(st, (size_t)(t + 1) * BKH);
        }

        const uint32_t s0 = sb + (t & 1) * STB;
        #pragma unroll
        for (int kk = 0; kk < BKH / 16; ++kk) {
            uint32_t ah[2][4], al[2][4];
            #pragma unroll
            for (int mt = 0; mt < 2; ++mt) {
                const uint32_t aaddr = s0 + (uint32_t)(warpM + mt * 16) * (PIT * 2)
                                       + lrow + kk * 32;
                LDMX4(ah[mt][0], ah[mt][1], ah[mt][2], ah[mt][3], aaddr);
                if (NT == 3)
                    LDMX4(al[mt][0], al[mt][1], al[mt][2], al[mt][3], aaddr + 2 * TILEB);
            }
            #pragma unroll
            for (int g = 0; g < 4; ++g) {
                const uint32_t baddr = s0 + (uint32_t)(warpN + g * 16) * (PIT * 2)
                                       + lrow + kk * 32;
                uint32_t bh0, bh1, bh2, bh3;
                LDMX4(bh0, bh1, bh2, bh3, baddr + 1 * TILEB);
                if (NT == 3) {
                    uint32_t bl0, bl1, bl2, bl3;
                    LDMX4(bl0, bl1, bl2, bl3, baddr + 3 * TILEB);
                    #pragma unroll
                    for (int mt = 0; mt < 2; ++mt) {
                        MMA16816(acc[mt][2 * g],     ah[mt], bh0, bh2);
                        MMA16816(acc[mt][2 * g],     ah[mt], bl0, bl2);
                        MMA16816(acc[mt][2 * g],     al[mt], bh0, bh2);
                        MMA16816(acc[mt][2 * g + 1], ah[mt], bh1, bh3);
                        MMA16816(acc[mt][2 * g + 1], ah[mt], bl1, bl3);
                        MMA16816(acc[mt][2 * g + 1], al[mt], bh1, bh3);
                    }
                } else {
                    #pragma unroll
                    for (int mt = 0; mt < 2; ++mt) {
                        MMA16816(acc[mt][2 * g],     ah[mt], bh0, bh2);
                        MMA16816(acc[mt][2 * g + 1], ah[mt], bh1, bh3);
                    }
                }
            }
        }
    }
    #undef ISSUE_STAGE

    // ---- epilogue: direct fp32 stores (quad-contiguous 32B segments) ----
    #pragma unroll
    for (int mt = 0; mt < 2; ++mt) {
        #pragma unroll
        for (int nf = 0; nf < 8; ++nf) {
            const int row = bm + warpM + mt * 16 + (lane >> 2);
            const int col = bn + warpN + nf * 8 + (lane & 3) * 2;
            *(float2*)&Out[(size_t)row * ldc + col] =
                make_float2(acc[mt][nf][0], acc[mt][nf][1]);
            *(float2*)&Out[(size_t)(row + 8) * ldc + col] =
                make_float2(acc[mt][nf][2], acc[mt][nf][3]);
        }
    }
}

// ---------------------------------------------------------------------------
// Row softmax over C=4096, in place. One block (256 threads) per row.
// ---------------------------------------------------------------------------
__global__ __launch_bounds__(256)
void softmax4096(float* __restrict__ A) {
    const int C = PC;
    float* row = A + (size_t)blockIdx.x * C;
    const int tid = threadIdx.x;
    const int lane = tid & 31;
    const int warp = tid >> 5;

    __shared__ float redmax[8];
    __shared__ float redsum[8];

    float4 v[4];
    float mx = -1e30f;
    #pragma unroll
    for (int j = 0; j < 4; j++) {
        v[j] = ((const float4*)row)[tid + j * 256];
        mx = fmaxf(mx, fmaxf(fmaxf(v[j].x, v[j].y), fmaxf(v[j].z, v[j].w)));
    }
    #pragma unroll
    for (int o = 16; o > 0; o >>= 1)
        mx = fmaxf(mx, __shfl_xor_sync(0xFFFFFFFFu, mx, o));
    if (lane == 0) redmax[warp] = mx;
    __syncthreads();
    mx = redmax[0];
    #pragma unroll
    for (int w = 1; w < 8; w++) mx = fmaxf(mx, redmax[w]);

    float s = 0.0f;
    #pragma unroll
    for (int j = 0; j < 4; j++) {
        v[j].x = __expf(v[j].x - mx);
        v[j].y = __expf(v[j].y - mx);
        v[j].z = __expf(v[j].z - mx);
        v[j].w = __expf(v[j].w - mx);
        s += (v[j].x + v[j].y) + (v[j].z + v[j].w);
    }
    #pragma unroll
    for (int o = 16; o > 0; o >>= 1)
        s += __shfl_xor_sync(0xFFFFFFFFu, s, o);
    if (lane == 0) redsum[warp] = s;
    __syncthreads();
    s = redsum[0];
    #pragma unroll
    for (int w = 1; w < 8; w++) s += redsum[w];

    const float rinv = 1.0f / s;
    #pragma unroll
    for (int j = 0; j < 4; j++) {
        v[j].x *= rinv; v[j].y *= rinv; v[j].z *= rinv; v[j].w *= rinv;
        ((float4*)row)[tid + j * 256] = v[j];
    }
}

// ===========================================================================
// Launch.  d_out layout: [output (B*C*D floats) | A (B*S*C floats)]
// ===========================================================================
extern "C" void kernel_launch(void* const* d_in, const int* in_sizes, int n_in,
                              void* d_out, int out_size) {
    const float* x = (const float*)d_in[0];    // [B,S,D]
    const float* lab = (const float*)d_in[1];  // [C,D]
    float* out = (float*)d_out;
    float* Aout = out + (size_t)PB * PC * PD;  // [B*S, C]

    void *pXh, *pXl, *pLh, *pLl, *pXhT, *pAhT;
    cudaGetSymbolAddress(&pXh, g_Xh);   cudaGetSymbolAddress(&pXl, g_Xl);
    cudaGetSymbolAddress(&pLh, g_Lh);   cudaGetSymbolAddress(&pLl, g_Ll);
    cudaGetSymbolAddress(&pXhT, g_XhT); cudaGetSymbolAddress(&pAhT, g_AhT);

    // GEMM1: NT=3, BK=32 -> stage = 4*128*40*2 = 40960 B, 2 stages
    const int SMEM_G1 = 2 * 4 * 128 * 40 * 2;
    // GEMM2: NT=1, BK=64 -> stage = 2*128*72*2 = 36864 B, 2 stages
    const int SMEM_G2 = 2 * 2 * 128 * 72 * 2;
    cudaFuncSetAttribute((const void*)gemm_hmma<3, 32>,
                         cudaFuncAttributeMaxDynamicSharedMemorySize, SMEM_G1);
    cudaFuncSetAttribute((const void*)gemm_hmma<1, 64>,
                         cudaFuncAttributeMaxDynamicSharedMemorySize, SMEM_G2);

    // 1. fp16 splits of X and L
    split_kernel<<<(PB * PS * PD / 4 + 255) / 256, 256>>>(
        x, (__half*)pXh, (__half*)pXl, PB * PS * PD / 4);
    split_kernel<<<(PC * PD / 4 + 255) / 256, 256>>>(
        lab, (__half*)pLh, (__half*)pLl, PC * PD / 4);

    // 2. X^T (hi only) per batch: [S,D] -> [D,S]
    {
        dim3 g(PD / 32, PS / 64, PB);
        transpose_h<<<g, 256>>>(x, (__half*)pXhT, PS, PD,
                                (size_t)PS * PD, (size_t)PD * PS);
    }

    // 3. GEMM1 (split-fp16, 3 terms): scores[B*S, C] = X @ L^T
    {
        dim3 g(PC / BN, (PB * PS) / BM, 1);
        gemm_hmma<3, 32><<<g, 256, SMEM_G1>>>(
            (const __half*)pXh, (const __half*)pXl,
            (const __half*)pLh, (const __half*)pLl,
            Aout, PD, PD, PC, PD, 0, 0, 0);
    }

    // 4. softmax over C, in place
    softmax4096<<<PB * PS, 256>>>(Aout);

    // 5. A^T (hi only) per batch: [S,C] -> [C,S]
    {
        dim3 g(PC / 32, PS / 64, PB);
        transpose_h<<<g, 256>>>(Aout, (__half*)pAhT, PS, PC,
                                (size_t)PS * PC, (size_t)PC * PS);
    }

    // 6. GEMM2 (pure fp16): out[C, D] = A^T @ X   per batch
    {
        dim3 g(PD / BN, PC / BM, PB);
        gemm_hmma<1, 64><<<g, 256, SMEM_G2>>>(
            (const __half*)pAhT, (const __half*)pAhT,
            (const __half*)pXhT, (const __half*)pXhT,
            out, PS, PS, PD, PS,
            (size_t)PC * PS, (size_t)PD * PS, (size_t)PC * PD);
    }
}